// round 7
// baseline (speedup 1.0000x reference)
#include <cuda_runtime.h>
#include <cuda_bf16.h>

// BPMLL loss, factorized:
//   inner[b]  = (sum_{t==0} exp(x)) * (sum_{t==1} exp(-x))
//   length[b] = n_pos * n_neg
//   out       = sum_b inner[b] / length[b]
//
// B = 128, L = 1024, target int32.
//
// R7: 128 blocks x 256 threads. Mainloop converts each exp term to 2^16
// fixed point for free (exp(+-x)*2^16 = ex2(fma(x, +-log2e, 16))), so the
// entire warp reduction collapses to three single-instruction
// redux.sync.add.u32 ops (sm_103 supports integer redux; f32 redux does not
// exist). No ballots, no shfl chains. Integer adds everywhere ->
// bit-deterministic. Finish: single u64 fixed-point atomic (low 56 bits =
// 2^32 fixed-point loss sum, high 8 bits = arrival counter).

__device__ unsigned long long g_acc = 0ULL;

#define CNT_ONE   (1ULL << 56)
#define VAL_MASK  (CNT_ONE - 1ULL)
#define FP_SCALE  4294967296.0      // 2^32 (final loss packing)
#define INV_S16   (1.0 / 65536.0)   // 2^-16 (per-row exp fixed point)

__device__ __forceinline__ float ex2_approx(float x) {
    float r;
    asm("ex2.approx.f32 %0, %1;" : "=f"(r) : "f"(x));
    return r;
}

template<int BLOCK>
__global__ void __launch_bounds__(BLOCK, 1)
bpmll_fused_kernel(const float* __restrict__ inp,
                   const int* __restrict__ tgt,
                   float* __restrict__ out,
                   int L, int B) {
    const int b = blockIdx.x;
    const float4* __restrict__ x4 = (const float4*)(inp + (size_t)b * L);
    const int4*   __restrict__ t4 = (const int4*)(tgt + (size_t)b * L);
    const int nvec = L >> 2;   // 256 for L=1024 -> one element per thread

    const float L2E = 1.4426950408889634f;   // log2(e)

    unsigned int sn = 0u;   // sum exp(x)*2^16 over negatives
    unsigned int sp = 0u;   // sum exp(-x)*2^16 over positives
    unsigned int np = 0u;   // count of positives

    for (int i = threadIdx.x; i < nvec; i += BLOCK) {
        float4 v = x4[i];
        int4   t = t4[i];
        {
            bool p = (t.x == 1);
            unsigned int e = __float2uint_rn(ex2_approx(fmaf(v.x, p ? -L2E : L2E, 16.0f)));
            sp += p ? e : 0u;  sn += p ? 0u : e;  np += (unsigned)t.x;
        }
        {
            bool p = (t.y == 1);
            unsigned int e = __float2uint_rn(ex2_approx(fmaf(v.y, p ? -L2E : L2E, 16.0f)));
            sp += p ? e : 0u;  sn += p ? 0u : e;  np += (unsigned)t.y;
        }
        {
            bool p = (t.z == 1);
            unsigned int e = __float2uint_rn(ex2_approx(fmaf(v.z, p ? -L2E : L2E, 16.0f)));
            sp += p ? e : 0u;  sn += p ? 0u : e;  np += (unsigned)t.z;
        }
        {
            bool p = (t.w == 1);
            unsigned int e = __float2uint_rn(ex2_approx(fmaf(v.w, p ? -L2E : L2E, 16.0f)));
            sp += p ? e : 0u;  sn += p ? 0u : e;  np += (unsigned)t.w;
        }
    }

    // single-instruction integer warp reductions (sm_103: REDUX.SUM.U32)
    sn = __reduce_add_sync(0xffffffffu, sn);
    sp = __reduce_add_sync(0xffffffffu, sp);
    np = __reduce_add_sync(0xffffffffu, np);

    constexpr int NWARP = BLOCK / 32;
    __shared__ unsigned int sh_sn[NWARP], sh_sp[NWARP], sh_np[NWARP];
    const int wid = threadIdx.x >> 5;
    const int lid = threadIdx.x & 31;
    if (lid == 0) { sh_sn[wid] = sn; sh_sp[wid] = sp; sh_np[wid] = np; }
    __syncthreads();

    if (threadIdx.x == 0) {
        unsigned long long tn = 0ULL, tp = 0ULL;
        unsigned int n = 0u;
        #pragma unroll
        for (int w = 0; w < NWARP; ++w) { tn += sh_sn[w]; tp += sh_sp[w]; n += sh_np[w]; }

        double dn = (double)tn * INV_S16;        // sum exp(x) over negatives
        double dp = (double)tp * INV_S16;        // sum exp(-x) over positives
        double len = (double)n * (double)(L - (int)n);
        double loss = (dn * dp) / len;

        unsigned long long myval =
            (unsigned long long)llrint(loss * FP_SCALE) + CNT_ONE;
        unsigned long long old = atomicAdd(&g_acc, myval);

        if ((old >> 56) == (unsigned long long)(B - 1)) {
            unsigned long long total = (old + myval) & VAL_MASK;
            out[0] = (float)((double)total * (1.0 / FP_SCALE));
            g_acc = 0ULL;   // reset for next graph replay
        }
    }
}

extern "C" void kernel_launch(void* const* d_in, const int* in_sizes, int n_in,
                              void* d_out, int out_size) {
    const float* inp = (const float*)d_in[0];
    const int*   tgt = (const int*)d_in[1];
    float* out = (float*)d_out;

    const int B = 128;
    const int L = in_sizes[0] / B;   // 1024

    constexpr int BLOCK = 256;
    bpmll_fused_kernel<BLOCK><<<B, BLOCK>>>(inp, tgt, out, L, B);
}

// round 8
// speedup vs baseline: 1.0437x; 1.0437x over previous
#include <cuda_runtime.h>
#include <cuda_bf16.h>

// BPMLL loss, factorized:
//   inner[b]  = (sum_{t==0} exp(x)) * (sum_{t==1} exp(-x))
//   length[b] = n_pos * n_neg
//   out       = sum_b inner[b] / length[b]
//
// B = 128, L = 1024, target int32.
//
// R8: ONE WARP PER ROW. grid = 128 blocks x 32 threads (one warp per SM).
// Each lane: 8 x (float4 + int4) loads (MLP=16), float exp-sums, integer
// n_pos (targets are 0/1 -> plain adds, no ballot/F2I). Reduce = two
// interleaved f32 shfl chains + one REDUX.SUM.U32 for n_pos. No
// __syncthreads, no smem, no cross-warp stage -> shortest possible tail.
// Finish: single u64 fixed-point atomic per warp (low 56 bits = 2^32
// fixed-point loss sum, high 8 bits = arrival counter) -> bit-deterministic.

__device__ unsigned long long g_acc = 0ULL;

#define CNT_ONE   (1ULL << 56)
#define VAL_MASK  (CNT_ONE - 1ULL)
#define FP_SCALE  4294967296.0   // 2^32

__global__ void __launch_bounds__(32, 1)
bpmll_warp_kernel(const float* __restrict__ inp,
                  const int* __restrict__ tgt,
                  float* __restrict__ out,
                  int L, int B) {
    const int b   = blockIdx.x;
    const int lid = threadIdx.x;   // 0..31
    const float4* __restrict__ x4 = (const float4*)(inp + (size_t)b * L);
    const int4*   __restrict__ t4 = (const int4*)(tgt + (size_t)b * L);

    // L=1024 -> 256 float4 per row -> 8 per lane. Batch all loads up front
    // for maximum memory-level parallelism (16 outstanding LDG.128).
    float4 v[8];
    int4   t[8];
    #pragma unroll
    for (int k = 0; k < 8; ++k) {
        v[k] = x4[lid + 32 * k];
        t[k] = t4[lid + 32 * k];
    }

    float s_neg  = 0.0f;   // sum exp(x) over negatives
    float s_pinv = 0.0f;   // sum exp(-x) over positives
    unsigned int np = 0u;  // positives count (targets are 0/1)

    #pragma unroll
    for (int k = 0; k < 8; ++k) {
        {
            bool p = (t[k].x == 1); float e = __expf(p ? -v[k].x : v[k].x);
            s_pinv += p ? e : 0.0f; s_neg += p ? 0.0f : e; np += (unsigned)t[k].x;
        }
        {
            bool p = (t[k].y == 1); float e = __expf(p ? -v[k].y : v[k].y);
            s_pinv += p ? e : 0.0f; s_neg += p ? 0.0f : e; np += (unsigned)t[k].y;
        }
        {
            bool p = (t[k].z == 1); float e = __expf(p ? -v[k].z : v[k].z);
            s_pinv += p ? e : 0.0f; s_neg += p ? 0.0f : e; np += (unsigned)t[k].z;
        }
        {
            bool p = (t[k].w == 1); float e = __expf(p ? -v[k].w : v[k].w);
            s_pinv += p ? e : 0.0f; s_neg += p ? 0.0f : e; np += (unsigned)t[k].w;
        }
    }

    // n_pos: single-instruction integer warp reduction (parallel with shfls)
    np = __reduce_add_sync(0xffffffffu, np);

    // two interleaved f32 shfl-xor chains
    #pragma unroll
    for (int off = 16; off > 0; off >>= 1) {
        s_neg  += __shfl_xor_sync(0xffffffffu, s_neg,  off);
        s_pinv += __shfl_xor_sync(0xffffffffu, s_pinv, off);
    }

    if (lid == 0) {
        float fnp = (float)np;
        float fnn = (float)L - fnp;
        float loss = (s_neg * s_pinv) / (fnp * fnn);

        unsigned long long myval =
            (unsigned long long)llrint((double)loss * FP_SCALE) + CNT_ONE;
        unsigned long long old = atomicAdd(&g_acc, myval);

        if ((old >> 56) == (unsigned long long)(B - 1)) {
            unsigned long long total = (old + myval) & VAL_MASK;
            out[0] = (float)((double)total * (1.0 / FP_SCALE));
            g_acc = 0ULL;   // reset for next graph replay
        }
    }
}

extern "C" void kernel_launch(void* const* d_in, const int* in_sizes, int n_in,
                              void* d_out, int out_size) {
    const float* inp = (const float*)d_in[0];
    const int*   tgt = (const int*)d_in[1];
    float* out = (float*)d_out;

    const int B = 128;
    const int L = in_sizes[0] / B;   // 1024

    bpmll_warp_kernel<<<B, 32>>>(inp, tgt, out, L, B);
}